// round 15
// baseline (speedup 1.0000x reference)
#include <cuda_runtime.h>
#include <cuda_bf16.h>
#include <math.h>
#include <stdint.h>

// ---- model constants ----
#define BB   2
#define TT   1024
#define RR   2048
#define DD   768
#define HH   12
#define KVHH 4
#define HDD  64
#define QKVW 1280
#define LLAY 6
#define VV   32000
#define FF   3072

typedef __nv_bfloat16 bf16;
typedef __nv_bfloat162 bf162;

// ---- scratch ----
__device__ float g_x  [RR*DD];
__device__ float g_x0 [RR*DD];
__device__ float g_xn [RR*DD];
__device__ float g_qkv[RR*QKVW];

__device__ bf16 g_xnh[RR*DD],  g_xnl[RR*DD];
__device__ bf16 g_yh [RR*DD],  g_yl [RR*DD];
__device__ bf16 g_hh [RR*FF],  g_hl [RR*FF];

__device__ bf16 g_wqkvh[LLAY*QKVW*DD], g_wqkvl[LLAY*QKVW*DD];
__device__ bf16 g_woh  [LLAY*DD*DD],   g_wol  [LLAY*DD*DD];
__device__ bf16 g_wfch [LLAY*FF*DD],   g_wfcl [LLAY*FF*DD];
__device__ bf16 g_wprh [LLAY*DD*FF],   g_wprl [LLAY*DD*FF];
__device__ bf16 g_lmh  [(size_t)VV*DD], g_lml [(size_t)VV*DD];

// ------------------------------------------------------------------
// helpers
// ------------------------------------------------------------------
__device__ __forceinline__ float block_reduce_sum_256(float v, float* sh) {
    int tid = threadIdx.x;
    sh[tid] = v;
    __syncthreads();
    #pragma unroll
    for (int s = 128; s > 0; s >>= 1) {
        if (tid < s) sh[tid] += sh[tid + s];
        __syncthreads();
    }
    return sh[0];
}
__device__ __forceinline__ float warp_reduce_sum(float v) {
    #pragma unroll
    for (int o = 16; o > 0; o >>= 1) v += __shfl_xor_sync(0xffffffffu, v, o);
    return v;
}
__device__ __forceinline__ float warp_reduce_max(float v) {
    #pragma unroll
    for (int o = 16; o > 0; o >>= 1) v = fmaxf(v, __shfl_xor_sync(0xffffffffu, v, o));
    return v;
}
__device__ __forceinline__ void split_store4(float4 v, bf16* hi, bf16* lo) {
    bf162 h0, h1, l0, l1;
    h0.x = __float2bfloat16_rn(v.x); h0.y = __float2bfloat16_rn(v.y);
    h1.x = __float2bfloat16_rn(v.z); h1.y = __float2bfloat16_rn(v.w);
    l0.x = __float2bfloat16_rn(v.x - __bfloat162float(h0.x));
    l0.y = __float2bfloat16_rn(v.y - __bfloat162float(h0.y));
    l1.x = __float2bfloat16_rn(v.z - __bfloat162float(h1.x));
    l1.y = __float2bfloat16_rn(v.w - __bfloat162float(h1.y));
    *(bf162*)hi = h0; *(bf162*)(hi + 2) = h1;
    *(bf162*)lo = l0; *(bf162*)(lo + 2) = l1;
}
__device__ __forceinline__ void split_store1(float v, bf16* hi, bf16* lo) {
    bf16 h = __float2bfloat16_rn(v);
    *hi = h;
    *lo = __float2bfloat16_rn(v - __bfloat162float(h));
}
__device__ __forceinline__ uint32_t smem_u32(const void* p) {
    uint32_t a;
    asm("{ .reg .u64 t; cvta.to.shared.u64 t, %1; cvt.u32.u64 %0, t; }" : "=r"(a) : "l"(p));
    return a;
}

// ------------------------------------------------------------------
// fp32 -> bf16 hi/lo split kernels
// ------------------------------------------------------------------
__global__ void split_kernel(const float* __restrict__ src,
                             bf16* __restrict__ hi, bf16* __restrict__ lo,
                             int n4) {
    int i = blockIdx.x * blockDim.x + threadIdx.x;
    if (i >= n4) return;
    float4 v = ((const float4*)src)[i];
    split_store4(v, hi + (size_t)i*4, lo + (size_t)i*4);
}
__global__ void pack_split_qkv(const float* __restrict__ Wq,
                               const float* __restrict__ Wk,
                               const float* __restrict__ Wv) {
    int i4 = blockIdx.x * blockDim.x + threadIdx.x;
    const int total4 = LLAY * QKVW * DD / 4;
    if (i4 >= total4) return;
    size_t e = (size_t)i4 * 4;
    int c   = (int)(e % DD);
    int r   = (int)((e / DD) % QKVW);
    int lyr = (int)(e / ((size_t)DD * QKVW));
    const float* srow;
    if (r < DD)            srow = Wq + (size_t)lyr*DD*DD  + (size_t)r*DD;
    else if (r < DD + 256) srow = Wk + (size_t)lyr*256*DD + (size_t)(r-DD)*DD;
    else                   srow = Wv + (size_t)lyr*256*DD + (size_t)(r-DD-256)*DD;
    float4 v = *(const float4*)(srow + c);
    split_store4(v, g_wqkvh + e, g_wqkvl + e);
}

// ------------------------------------------------------------------
// embedding + rmsnorm
// ------------------------------------------------------------------
__global__ void embed_norm_kernel(const int* __restrict__ idx,
                                  const float* __restrict__ wte) {
    __shared__ float sh[256];
    int row = blockIdx.x, tid = threadIdx.x;
    int tok = idx[row];
    const float* wrow = wte + (size_t)tok * DD;
    float v[3]; float ss = 0.f;
    #pragma unroll
    for (int j = 0; j < 3; ++j) { v[j] = wrow[tid + j*256]; ss += v[j]*v[j]; }
    float tot = block_reduce_sum_256(ss, sh);
    float sc = rsqrtf(tot * (1.0f/DD) + 1e-6f);
    #pragma unroll
    for (int j = 0; j < 3; ++j) {
        float o = v[j] * sc;
        g_x [(size_t)row*DD + tid + j*256] = o;
        g_x0[(size_t)row*DD + tid + j*256] = o;
    }
}

// ------------------------------------------------------------------
// residual mix + rmsnorm -> xn fp32 + bf16 hi/lo
// ------------------------------------------------------------------
__global__ void resid_norm_kernel(const float* __restrict__ rl,
                                  const float* __restrict__ xl,
                                  int li) {
    __shared__ float sh[256];
    int row = blockIdx.x, tid = threadIdx.x;
    float rs = 1.f, xs = 0.f;
    if (li >= 0) { rs = rl[li]; xs = xl[li]; }
    float v[3]; float ss = 0.f;
    #pragma unroll
    for (int j = 0; j < 3; ++j) {
        size_t i = (size_t)row*DD + tid + j*256;
        float val = g_x[i]*rs;
        if (li >= 0) val += g_x0[i]*xs;
        v[j] = val; ss += val*val;
    }
    float tot = block_reduce_sum_256(ss, sh);
    float sc = rsqrtf(tot * (1.0f/DD) + 1e-6f);
    #pragma unroll
    for (int j = 0; j < 3; ++j) {
        size_t i = (size_t)row*DD + tid + j*256;
        if (li >= 0) g_x[i] = v[j];
        float o = v[j]*sc;
        g_xn[i] = o;
        split_store1(o, &g_xnh[i], &g_xnl[i]);
    }
}

#define MMA_BF16(d, a, b)                                                     \
    asm volatile("mma.sync.aligned.m16n8k16.row.col.f32.bf16.bf16.f32 "       \
                 "{%0,%1,%2,%3},{%4,%5,%6,%7},{%8,%9},{%0,%1,%2,%3};"         \
                 : "+f"(d[0]), "+f"(d[1]), "+f"(d[2]), "+f"(d[3])             \
                 : "r"(a[0]), "r"(a[1]), "r"(a[2]), "r"(a[3]),                \
                   "r"(b[0]), "r"(b[1]));

#define LDSM4(r0, r1, r2, r3, addr)                                           \
    asm volatile("ldmatrix.sync.aligned.m8n8.x4.shared.b16 {%0,%1,%2,%3},[%4];" \
                 : "=r"(r0), "=r"(r1), "=r"(r2), "=r"(r3) : "r"(addr));

// ------------------------------------------------------------------
// 64x64 CTA-tile GEMM, 128 threads (4 warps, each 32x32), BK=32,
// 2-stage cp.async, 40KB smem, fragment software pipelining:
// ALL 16 ldmatrix for both k-chunks issued before the 48 mma, so
// the tensor stream runs uninterrupted across the whole 32-K tile.
// C[M,N] (+)= A[M,K]*B[N,K]^T  via Ah*Bh + Ah*Bl + Al*Bh.
// EPI: 0 store, 1 accumulate, 2 relu^2 -> bf16 hi/lo, 3 softcap tanh
// ------------------------------------------------------------------
#define PL64   5120                 // 64 rows * 80 bytes
#define ST64   (4*PL64)             // 20480
#define GSMB64 (2*ST64)             // 40960

template<int EPI>
__global__ void __launch_bounds__(128, 4)
gemm64_kernel(const bf16* __restrict__ Ah, const bf16* __restrict__ Al,
              const bf16* __restrict__ Bh, const bf16* __restrict__ Bl,
              float* __restrict__ C, bf16* __restrict__ Ch, bf16* __restrict__ Cl,
              int M, int N, int K) {
    extern __shared__ char dsm[];
    const uint32_t tiles = smem_u32(dsm);

    const int tid = threadIdx.x, lane = tid & 31, warp = tid >> 5;
    const int wm = warp & 1, wn = warp >> 1;
    const int bm = blockIdx.y * 64, bn = blockIdx.x * 64;

    const int row0 = tid >> 2;          // 0..31
    const int ch   = tid & 3;
    const bf16* Pb[4] = { Ah + (size_t)(bm + row0)*K + ch*8,
                          Al + (size_t)(bm + row0)*K + ch*8,
                          Bh + (size_t)(bn + row0)*K + ch*8,
                          Bl + (size_t)(bn + row0)*K + ch*8 };
    const uint32_t dst0 = (uint32_t)(row0*80 + ch*16);

    float acc[2][4][4];
    #pragma unroll
    for (int i = 0; i < 2; ++i)
        #pragma unroll
        for (int j = 0; j < 4; ++j)
            #pragma unroll
            for (int r = 0; r < 4; ++r) acc[i][j][r] = 0.f;

    const int nk = K >> 5;
    auto load_stage = [&](int kt) {
        if (kt < nk) {
            uint32_t sb = tiles + (uint32_t)(kt & 1)*ST64;
            #pragma unroll
            for (int pl = 0; pl < 4; ++pl)
                #pragma unroll
                for (int rr = 0; rr < 2; ++rr) {
                    uint32_t dst = sb + pl*PL64 + dst0 + rr*32*80;
                    const bf16* src = Pb[pl] + (size_t)(rr*32)*K + kt*32;
                    asm volatile("cp.async.cg.shared.global [%0], [%1], 16;"
                                 :: "r"(dst), "l"(src));
                }
        }
        asm volatile("cp.async.commit_group;");
    };

    const int arow  = wm*32 + (lane & 15);
    const int acolx = (lane >> 4) << 3;
    const int brow  = wn*32 + ((lane >> 4) << 3) + (lane & 7);
    const int bcolx = ((lane >> 3) & 1) << 3;

    load_stage(0);
    load_stage(1);

    for (int kt = 0; kt < nk; ++kt) {
        uint32_t sb = tiles + (uint32_t)(kt & 1)*ST64;
        if (kt == nk - 1) { asm volatile("cp.async.wait_group 0;"); }
        else              { asm volatile("cp.async.wait_group 1;"); }
        __syncthreads();

        // ---- fragment loads for BOTH k-chunks, A0/B0 first ----
        uint32_t ah[2][2][4], al[2][2][4], bh[2][4][2], bl[2][4][2];
        #pragma unroll
        for (int c = 0; c < 2; ++c) {
            const int kc = c * 16;
            #pragma unroll
            for (int mi = 0; mi < 2; ++mi) {
                uint32_t aaddr = sb + (arow + mi*16)*80 + (kc + acolx)*2;
                LDSM4(ah[c][mi][0], ah[c][mi][1], ah[c][mi][2], ah[c][mi][3], aaddr);
                LDSM4(al[c][mi][0], al[c][mi][1], al[c][mi][2], al[c][mi][3], aaddr + PL64);
            }
            #pragma unroll
            for (int nt = 0; nt < 2; ++nt) {
                uint32_t baddr = sb + 2*PL64 + (brow + nt*16)*80 + (kc + bcolx)*2;
                LDSM4(bh[c][nt*2][0], bh[c][nt*2][1], bh[c][nt*2+1][0], bh[c][nt*2+1][1], baddr);
                LDSM4(bl[c][nt*2][0], bl[c][nt*2][1], bl[c][nt*2+1][0], bl[c][nt*2+1][1], baddr + PL64);
            }
        }

        // ---- uninterrupted mma stream: 48 mma ----
        #pragma unroll
        for (int c = 0; c < 2; ++c) {
            #pragma unroll
            for (int mi = 0; mi < 2; ++mi)
                #pragma unroll
                for (int ni = 0; ni < 4; ++ni)
                    MMA_BF16(acc[mi][ni], ah[c][mi], bh[c][ni]);
            #pragma unroll
            for (int mi = 0; mi < 2; ++mi)
                #pragma unroll
                for (int ni = 0; ni < 4; ++ni)
                    MMA_BF16(acc[mi][ni], ah[c][mi], bl[c][ni]);
            #pragma unroll
            for (int mi = 0; mi < 2; ++mi)
                #pragma unroll
                for (int ni = 0; ni < 4; ++ni)
                    MMA_BF16(acc[mi][ni], al[c][mi], bh[c][ni]);
        }
        __syncthreads();
        load_stage(kt + 2);
    }

    const int fr = lane >> 2, fq = (lane & 3) << 1;
    #pragma unroll
    for (int mi = 0; mi < 2; ++mi) {
        #pragma unroll
        for (int ni = 0; ni < 4; ++ni) {
            int row = bm + wm*32 + mi*16 + fr;
            int col = bn + wn*32 + ni*8 + fq;
            #pragma unroll
            for (int r = 0; r < 4; ++r) {
                int rr = row + (r >> 1)*8;
                int cc = col + (r & 1);
                float val = acc[mi][ni][r];
                size_t ix = (size_t)rr * N + cc;
                if (EPI == 1) {
                    C[ix] += val;
                } else if (EPI == 2) {
                    float re = fmaxf(val, 0.f);
                    split_store1(re * re, &Ch[ix], &Cl[ix]);
                } else if (EPI == 3) {
                    C[ix] = 15.0f * tanhf(val * (1.0f/15.0f));
                } else {
                    C[ix] = val;
                }
            }
        }
    }
}

// ------------------------------------------------------------------
// value-embedding gate
// ------------------------------------------------------------------
__global__ void ve_kernel(const int* __restrict__ idx,
                          const float* __restrict__ ve_table,
                          const float* __restrict__ gate_w) {
    __shared__ float gates[KVHH];
    int row = blockIdx.x, tid = threadIdx.x;
    if (tid < KVHH*32) {
        int g = tid >> 5, lane = tid & 31;
        float p = g_xn[(size_t)row*DD + lane] * gate_w[g*32 + lane];
        p = warp_reduce_sum(p);
        if (lane == 0) gates[g] = 2.0f / (1.0f + expf(-p));
    }
    __syncthreads();
    int tok = idx[row];
    g_qkv[(size_t)row*QKVW + 1024 + tid] += gates[tid >> 6] *
        ve_table[(size_t)tok*256 + tid];
}

// ------------------------------------------------------------------
// RoPE + per-head rmsnorm
// ------------------------------------------------------------------
__global__ void rope_norm_kernel(float* __restrict__ p, int nh, int off) {
    int gw   = (blockIdx.x * blockDim.x + threadIdx.x) >> 5;
    int lane = threadIdx.x & 31;
    int row  = gw / nh;
    int head = gw - row*nh;
    int t    = row & (TT-1);
    float* base = p + (size_t)row*QKVW + off + head*HDD;
    float a = base[lane];
    float b = base[lane + 32];
    float inv = 1.0f / powf(10000.0f, (float)lane * (1.0f/32.0f));
    float ang = (float)t * inv;
    float s, c;
    sincosf(ang, &s, &c);
    float na =  a*c + b*s;
    float nb = -a*s + b*c;
    float ss = warp_reduce_sum(na*na + nb*nb);
    float sc = rsqrtf(ss * (1.0f/HDD) + 1e-6f);
    base[lane]      = na * sc;
    base[lane + 32] = nb * sc;
}

// ------------------------------------------------------------------
// tiled attention, QT=16 -> 512 blocks for higher SM occupancy.
// block per (b, kvh, 16-query tile); 8 warps, each warp owns
// 2 queries x 3 heads.
// ------------------------------------------------------------------
#define QT 16
__global__ void __launch_bounds__(256) attn_kernel(int w) {
    __shared__ float sq[QT*3][64];
    __shared__ float sk[32][68];
    __shared__ float sv[32][68];

    int tid = threadIdx.x, lane = tid & 31, warp = tid >> 5;
    int blk = blockIdx.x;
    int qt = blk & 63;
    int g  = (blk >> 6) & 3;
    int b  = blk >> 8;
    int q0 = qt * QT;

    for (int it = tid; it < QT*3*16; it += 256) {
        int qh = it >> 4, ds = (it & 15) << 2;
        int q = qh / 3, hl = qh % 3;
        const float* qp = g_qkv + (size_t)(b*TT + q0 + q)*QKVW + (g*3 + hl)*HDD + ds;
        *(float4*)&sq[qh][ds] = *(const float4*)qp;
    }

    float m[6], l[6], a0[6], a1[6];
    #pragma unroll
    for (int p = 0; p < 6; ++p) { m[p] = -1e30f; l[p] = 0.f; a0[p] = 0.f; a1[p] = 0.f; }

    int jlo = q0 - w + 1; if (jlo < 0) jlo = 0;
    int js0 = jlo & ~31;
    __syncthreads();

    for (int js = js0; js < q0 + QT; js += 32) {
        for (int it = tid; it < 512; it += 256) {
            int key = it >> 4, ds = (it & 15) << 2;
            const float* kp = g_qkv + (size_t)(b*TT + js + key)*QKVW + DD + g*HDD + ds;
            *(float4*)&sk[key][ds] = *(const float4*)kp;
            *(float4*)&sv[key][ds] = *(const float4*)(kp + 256);
        }
        __syncthreads();

        #pragma unroll
        for (int qi = 0; qi < 2; ++qi) {
            int qq = warp*2 + qi;
            int t  = q0 + qq;
            int j  = js + lane;
            bool valid = (j <= t) && (t - j < w);
            float s0 = -1e30f, s1 = -1e30f, s2 = -1e30f;
            if (valid) {
                float d0 = 0.f, d1 = 0.f, d2 = 0.f;
                #pragma unroll
                for (int ds = 0; ds < 64; ds += 4) {
                    float4 kv = *(const float4*)&sk[lane][ds];
                    float4 qa = *(const float4*)&sq[qq*3+0][ds];
                    float4 qb = *(const float4*)&sq[qq*3+1][ds];
                    float4 qc = *(const float4*)&sq[qq*3+2][ds];
                    d0 += qa.x*kv.x + qa.y*kv.y + qa.z*kv.z + qa.w*kv.w;
                    d1 += qb.x*kv.x + qb.y*kv.y + qb.z*kv.z + qb.w*kv.w;
                    d2 += qc.x*kv.x + qc.y*kv.y + qc.z*kv.z + qc.w*kv.w;
                }
                s0 = d0*0.125f; s1 = d1*0.125f; s2 = d2*0.125f;
            }
            float pr0, pr1, pr2;
            #pragma unroll
            for (int hl = 0; hl < 3; ++hl) {
                int p = qi*3 + hl;
                float sc = (hl == 0) ? s0 : (hl == 1) ? s1 : s2;
                float cm = warp_reduce_max(sc);
                float nm = fmaxf(m[p], cm);
                float pr = valid ? __expf(sc - nm) : 0.f;
                float corr = __expf(m[p] - nm);
                float sl = warp_reduce_sum(pr);
                l[p]  = l[p]*corr + sl;
                a0[p] *= corr; a1[p] *= corr;
                m[p] = nm;
                if (hl == 0) pr0 = pr; else if (hl == 1) pr1 = pr; else pr2 = pr;
            }
            #pragma unroll 8
            for (int kk = 0; kk < 32; ++kk) {
                float v0 = sv[kk][lane], v1 = sv[kk][lane+32];
                float pa = __shfl_sync(0xffffffffu, pr0, kk);
                float pb = __shfl_sync(0xffffffffu, pr1, kk);
                float pc = __shfl_sync(0xffffffffu, pr2, kk);
                a0[qi*3+0] = fmaf(pa, v0, a0[qi*3+0]);
                a1[qi*3+0] = fmaf(pa, v1, a1[qi*3+0]);
                a0[qi*3+1] = fmaf(pb, v0, a0[qi*3+1]);
                a1[qi*3+1] = fmaf(pb, v1, a1[qi*3+1]);
                a0[qi*3+2] = fmaf(pc, v0, a0[qi*3+2]);
                a1[qi*3+2] = fmaf(pc, v1, a1[qi*3+2]);
            }
        }
        __syncthreads();
    }

    #pragma unroll
    for (int qi = 0; qi < 2; ++qi) {
        #pragma unroll
        for (int hl = 0; hl < 3; ++hl) {
            int p = qi*3 + hl;
            size_t off = (size_t)(b*TT + q0 + warp*2 + qi)*DD + (g*3 + hl)*HDD;
            float inv = 1.0f / l[p];
            split_store1(a0[p]*inv, &g_yh[off + lane],      &g_yl[off + lane]);
            split_store1(a1[p]*inv, &g_yh[off + lane + 32], &g_yl[off + lane + 32]);
        }
    }
}

// ------------------------------------------------------------------
// host launcher
// ------------------------------------------------------------------
extern "C" void kernel_launch(void* const* d_in, const int* in_sizes, int n_in,
                              void* d_out, int out_size) {
    (void)in_sizes; (void)n_in; (void)out_size;
    const int*   idx    = (const int*)  d_in[0];
    const float* wte    = (const float*)d_in[1];
    const float* Wq     = (const float*)d_in[2];
    const float* Wk     = (const float*)d_in[3];
    const float* Wv     = (const float*)d_in[4];
    const float* Wo     = (const float*)d_in[5];
    const float* Wfc    = (const float*)d_in[6];
    const float* Wproj  = (const float*)d_in[7];
    const float* vetab  = (const float*)d_in[8];
    const float* vegate = (const float*)d_in[9];
    const float* rl     = (const float*)d_in[10];
    const float* xl     = (const float*)d_in[11];
    const float* lm     = (const float*)d_in[12];
    float* out = (float*)d_out;

    float *px, *pqkv;
    bf16 *pxnh, *pxnl, *pyh, *pyl, *phh, *phl;
    bf16 *pwqkvh, *pwqkvl, *pwoh, *pwol, *pwfch, *pwfcl, *pwprh, *pwprl, *plmh, *plml;
    cudaGetSymbolAddress((void**)&px,    g_x);
    cudaGetSymbolAddress((void**)&pqkv,  g_qkv);
    cudaGetSymbolAddress((void**)&pxnh,  g_xnh);
    cudaGetSymbolAddress((void**)&pxnl,  g_xnl);
    cudaGetSymbolAddress((void**)&pyh,   g_yh);
    cudaGetSymbolAddress((void**)&pyl,   g_yl);
    cudaGetSymbolAddress((void**)&phh,   g_hh);
    cudaGetSymbolAddress((void**)&phl,   g_hl);
    cudaGetSymbolAddress((void**)&pwqkvh,g_wqkvh);
    cudaGetSymbolAddress((void**)&pwqkvl,g_wqkvl);
    cudaGetSymbolAddress((void**)&pwoh,  g_woh);
    cudaGetSymbolAddress((void**)&pwol,  g_wol);
    cudaGetSymbolAddress((void**)&pwfch, g_wfch);
    cudaGetSymbolAddress((void**)&pwfcl, g_wfcl);
    cudaGetSymbolAddress((void**)&pwprh, g_wprh);
    cudaGetSymbolAddress((void**)&pwprl, g_wprl);
    cudaGetSymbolAddress((void**)&plmh,  g_lmh);
    cudaGetSymbolAddress((void**)&plml,  g_lml);

    cudaFuncSetAttribute((const void*)gemm64_kernel<0>, cudaFuncAttributeMaxDynamicSharedMemorySize, GSMB64);
    cudaFuncSetAttribute((const void*)gemm64_kernel<1>, cudaFuncAttributeMaxDynamicSharedMemorySize, GSMB64);
    cudaFuncSetAttribute((const void*)gemm64_kernel<2>, cudaFuncAttributeMaxDynamicSharedMemorySize, GSMB64);
    cudaFuncSetAttribute((const void*)gemm64_kernel<3>, cudaFuncAttributeMaxDynamicSharedMemorySize, GSMB64);

    const int windows[LLAY] = {TT/2, TT, TT/2, TT, TT/2, TT};
    bf16* nb = (bf16*)0;
    int n4;

    // launches 1-3, then the profiled QKV GEMM at launch 4
    n4 = LLAY*QKVW*DD/4;  pack_split_qkv<<<(n4+255)/256, 256>>>(Wq, Wk, Wv);     // 1
    embed_norm_kernel<<<RR, 256>>>(idx, wte);                                    // 2
    resid_norm_kernel<<<RR, 256>>>(rl, xl, 0);                                   // 3
    gemm64_kernel<0><<<dim3(QKVW/64, RR/64), 128, GSMB64>>>(                     // 4
        pxnh, pxnl, pwqkvh, pwqkvl, pqkv, nb, nb, RR, QKVW, DD);

    // remaining weight splits
    n4 = LLAY*DD*DD/4;    split_kernel<<<(n4+255)/256, 256>>>(Wo,    pwoh,  pwol,  n4);
    n4 = LLAY*FF*DD/4;    split_kernel<<<(n4+255)/256, 256>>>(Wfc,   pwfch, pwfcl, n4);
    n4 = LLAY*DD*FF/4;    split_kernel<<<(n4+255)/256, 256>>>(Wproj, pwprh, pwprl, n4);
    n4 = VV*DD/4;         split_kernel<<<(n4+255)/256, 256>>>(lm,    plmh,  plml,  n4);

    for (int i = 0; i < LLAY; ++i) {
        if (i > 0) {
            resid_norm_kernel<<<RR, 256>>>(rl, xl, i);
            gemm64_kernel<0><<<dim3(QKVW/64, RR/64), 128, GSMB64>>>(
                pxnh, pxnl, pwqkvh + (size_t)i*QKVW*DD, pwqkvl + (size_t)i*QKVW*DD,
                pqkv, nb, nb, RR, QKVW, DD);
        }

        int slot = (i == 1) ? 0 : (i == 3) ? 1 : (i == 5) ? 2 : -1;
        if (slot >= 0)
            ve_kernel<<<RR, 256>>>(idx, vetab + (size_t)slot*VV*256,
                                   vegate + (size_t)slot*KVHH*32);

        rope_norm_kernel<<<(RR*HH)/8,   256>>>(pqkv, HH,   0);
        rope_norm_kernel<<<(RR*KVHH)/8, 256>>>(pqkv, KVHH, DD);

        attn_kernel<<<BB*KVHH*(TT/QT), 256>>>(windows[i]);

        gemm64_kernel<1><<<dim3(DD/64, RR/64), 128, GSMB64>>>(
            pyh, pyl, pwoh + (size_t)i*DD*DD, pwol + (size_t)i*DD*DD,
            px, nb, nb, RR, DD, DD);

        resid_norm_kernel<<<RR, 256>>>(rl, xl, -1);

        gemm64_kernel<2><<<dim3(FF/64, RR/64), 128, GSMB64>>>(
            pxnh, pxnl, pwfch + (size_t)i*FF*DD, pwfcl + (size_t)i*FF*DD,
            px, phh, phl, RR, FF, DD);

        gemm64_kernel<1><<<dim3(DD/64, RR/64), 128, GSMB64>>>(
            phh, phl, pwprh + (size_t)i*DD*FF, pwprl + (size_t)i*DD*FF,
            px, nb, nb, RR, DD, FF);
    }

    resid_norm_kernel<<<RR, 256>>>(rl, xl, -1);
    gemm64_kernel<3><<<dim3(VV/64, RR/64), 128, GSMB64>>>(
        pxnh, pxnl, plmh, plml, out, nb, nb, RR, VV, DD);
}

// round 16
// speedup vs baseline: 1.0230x; 1.0230x over previous
#include <cuda_runtime.h>
#include <cuda_bf16.h>
#include <math.h>
#include <stdint.h>

// ---- model constants ----
#define BB   2
#define TT   1024
#define RR   2048
#define DD   768
#define HH   12
#define KVHH 4
#define HDD  64
#define QKVW 1280
#define LLAY 6
#define VV   32000
#define FF   3072

typedef __nv_bfloat16 bf16;
typedef __nv_bfloat162 bf162;

// ---- scratch ----
__device__ float g_x  [RR*DD];
__device__ float g_x0 [RR*DD];
__device__ float g_xn [RR*DD];     // fp32 xn; only cols [0,32) consumed (ve gate)
__device__ float g_qkv[RR*QKVW];

__device__ bf16 g_xnh[RR*DD],  g_xnl[RR*DD];
__device__ bf16 g_yh [RR*DD],  g_yl [RR*DD];
__device__ bf16 g_hh [RR*FF],  g_hl [RR*FF];

__device__ bf16 g_wqkvh[LLAY*QKVW*DD], g_wqkvl[LLAY*QKVW*DD];
__device__ bf16 g_woh  [LLAY*DD*DD],   g_wol  [LLAY*DD*DD];
__device__ bf16 g_wfch [LLAY*FF*DD],   g_wfcl [LLAY*FF*DD];
__device__ bf16 g_wprh [LLAY*DD*FF],   g_wprl [LLAY*DD*FF];
__device__ bf16 g_lmh  [(size_t)VV*DD], g_lml [(size_t)VV*DD];

// ------------------------------------------------------------------
// helpers
// ------------------------------------------------------------------
__device__ __forceinline__ float block_reduce_sum_256(float v, float* sh) {
    int tid = threadIdx.x;
    sh[tid] = v;
    __syncthreads();
    #pragma unroll
    for (int s = 128; s > 0; s >>= 1) {
        if (tid < s) sh[tid] += sh[tid + s];
        __syncthreads();
    }
    return sh[0];
}
__device__ __forceinline__ float warp_reduce_sum(float v) {
    #pragma unroll
    for (int o = 16; o > 0; o >>= 1) v += __shfl_xor_sync(0xffffffffu, v, o);
    return v;
}
__device__ __forceinline__ float warp_reduce_max(float v) {
    #pragma unroll
    for (int o = 16; o > 0; o >>= 1) v = fmaxf(v, __shfl_xor_sync(0xffffffffu, v, o));
    return v;
}
__device__ __forceinline__ void split_store4(float4 v, bf16* hi, bf16* lo) {
    bf162 h0, h1, l0, l1;
    h0.x = __float2bfloat16_rn(v.x); h0.y = __float2bfloat16_rn(v.y);
    h1.x = __float2bfloat16_rn(v.z); h1.y = __float2bfloat16_rn(v.w);
    l0.x = __float2bfloat16_rn(v.x - __bfloat162float(h0.x));
    l0.y = __float2bfloat16_rn(v.y - __bfloat162float(h0.y));
    l1.x = __float2bfloat16_rn(v.z - __bfloat162float(h1.x));
    l1.y = __float2bfloat16_rn(v.w - __bfloat162float(h1.y));
    *(bf162*)hi = h0; *(bf162*)(hi + 2) = h1;
    *(bf162*)lo = l0; *(bf162*)(lo + 2) = l1;
}
__device__ __forceinline__ void split_store1(float v, bf16* hi, bf16* lo) {
    bf16 h = __float2bfloat16_rn(v);
    *hi = h;
    *lo = __float2bfloat16_rn(v - __bfloat162float(h));
}
__device__ __forceinline__ uint32_t smem_u32(const void* p) {
    uint32_t a;
    asm("{ .reg .u64 t; cvta.to.shared.u64 t, %1; cvt.u32.u64 %0, t; }" : "=r"(a) : "l"(p));
    return a;
}

// ------------------------------------------------------------------
// fp32 -> bf16 hi/lo split kernels
// ------------------------------------------------------------------
__global__ void split_kernel(const float* __restrict__ src,
                             bf16* __restrict__ hi, bf16* __restrict__ lo,
                             int n4) {
    int i = blockIdx.x * blockDim.x + threadIdx.x;
    if (i >= n4) return;
    float4 v = ((const float4*)src)[i];
    split_store4(v, hi + (size_t)i*4, lo + (size_t)i*4);
}
__global__ void pack_split_qkv(const float* __restrict__ Wq,
                               const float* __restrict__ Wk,
                               const float* __restrict__ Wv) {
    int i4 = blockIdx.x * blockDim.x + threadIdx.x;
    const int total4 = LLAY * QKVW * DD / 4;
    if (i4 >= total4) return;
    size_t e = (size_t)i4 * 4;
    int c   = (int)(e % DD);
    int r   = (int)((e / DD) % QKVW);
    int lyr = (int)(e / ((size_t)DD * QKVW));
    const float* srow;
    if (r < DD)            srow = Wq + (size_t)lyr*DD*DD  + (size_t)r*DD;
    else if (r < DD + 256) srow = Wk + (size_t)lyr*256*DD + (size_t)(r-DD)*DD;
    else                   srow = Wv + (size_t)lyr*256*DD + (size_t)(r-DD-256)*DD;
    float4 v = *(const float4*)(srow + c);
    split_store4(v, g_wqkvh + e, g_wqkvl + e);
}

// ------------------------------------------------------------------
// embedding + rmsnorm
// ------------------------------------------------------------------
__global__ void embed_norm_kernel(const int* __restrict__ idx,
                                  const float* __restrict__ wte) {
    __shared__ float sh[256];
    int row = blockIdx.x, tid = threadIdx.x;
    int tok = idx[row];
    const float* wrow = wte + (size_t)tok * DD;
    float v[3]; float ss = 0.f;
    #pragma unroll
    for (int j = 0; j < 3; ++j) { v[j] = wrow[tid + j*256]; ss += v[j]*v[j]; }
    float tot = block_reduce_sum_256(ss, sh);
    float sc = rsqrtf(tot * (1.0f/DD) + 1e-6f);
    #pragma unroll
    for (int j = 0; j < 3; ++j) {
        float o = v[j] * sc;
        g_x [(size_t)row*DD + tid + j*256] = o;
        g_x0[(size_t)row*DD + tid + j*256] = o;
    }
}

// ------------------------------------------------------------------
// residual mix + rmsnorm -> bf16 hi/lo planes (+ fp32 xn cols [0,32))
// ------------------------------------------------------------------
__global__ void resid_norm_kernel(const float* __restrict__ rl,
                                  const float* __restrict__ xl,
                                  int li) {
    __shared__ float sh[256];
    int row = blockIdx.x, tid = threadIdx.x;
    float rs = 1.f, xs = 0.f;
    if (li >= 0) { rs = rl[li]; xs = xl[li]; }
    float v[3]; float ss = 0.f;
    #pragma unroll
    for (int j = 0; j < 3; ++j) {
        size_t i = (size_t)row*DD + tid + j*256;
        float val = g_x[i]*rs;
        if (li >= 0) val += g_x0[i]*xs;
        v[j] = val; ss += val*val;
    }
    float tot = block_reduce_sum_256(ss, sh);
    float sc = rsqrtf(tot * (1.0f/DD) + 1e-6f);
    #pragma unroll
    for (int j = 0; j < 3; ++j) {
        size_t i = (size_t)row*DD + tid + j*256;
        if (li >= 0) g_x[i] = v[j];
        float o = v[j]*sc;
        if (j == 0 && tid < 32) g_xn[i] = o;    // only ve-gate columns needed
        split_store1(o, &g_xnh[i], &g_xnl[i]);
    }
}

#define MMA_BF16(d, a, b)                                                     \
    asm volatile("mma.sync.aligned.m16n8k16.row.col.f32.bf16.bf16.f32 "       \
                 "{%0,%1,%2,%3},{%4,%5,%6,%7},{%8,%9},{%0,%1,%2,%3};"         \
                 : "+f"(d[0]), "+f"(d[1]), "+f"(d[2]), "+f"(d[3])             \
                 : "r"(a[0]), "r"(a[1]), "r"(a[2]), "r"(a[3]),                \
                   "r"(b[0]), "r"(b[1]));

#define LDSM4(r0, r1, r2, r3, addr)                                           \
    asm volatile("ldmatrix.sync.aligned.m8n8.x4.shared.b16 {%0,%1,%2,%3},[%4];" \
                 : "=r"(r0), "=r"(r1), "=r"(r2), "=r"(r3) : "r"(addr));

// ------------------------------------------------------------------
// 64x64 CTA-tile GEMM, 128 threads (4 warps, each 32x32), BK=32,
// 2-stage cp.async, 40KB smem -> high CTA residency (R12 proven config).
// C[M,N] (+)= A[M,K]*B[N,K]^T  via Ah*Bh + Ah*Bl + Al*Bh.
// EPI: 0 store, 1 accumulate, 2 relu^2 -> bf16 hi/lo, 3 softcap tanh
// ------------------------------------------------------------------
#define PL64   5120                 // 64 rows * 80 bytes
#define ST64   (4*PL64)             // 20480
#define GSMB64 (2*ST64)             // 40960

template<int EPI>
__global__ void __launch_bounds__(128, 5)
gemm64_kernel(const bf16* __restrict__ Ah, const bf16* __restrict__ Al,
              const bf16* __restrict__ Bh, const bf16* __restrict__ Bl,
              float* __restrict__ C, bf16* __restrict__ Ch, bf16* __restrict__ Cl,
              int M, int N, int K) {
    extern __shared__ char dsm[];
    const uint32_t tiles = smem_u32(dsm);

    const int tid = threadIdx.x, lane = tid & 31, warp = tid >> 5;
    const int wm = warp & 1, wn = warp >> 1;
    const int bm = blockIdx.y * 64, bn = blockIdx.x * 64;

    const int row0 = tid >> 2;          // 0..31
    const int ch   = tid & 3;
    const bf16* Pb[4] = { Ah + (size_t)(bm + row0)*K + ch*8,
                          Al + (size_t)(bm + row0)*K + ch*8,
                          Bh + (size_t)(bn + row0)*K + ch*8,
                          Bl + (size_t)(bn + row0)*K + ch*8 };
    const uint32_t dst0 = (uint32_t)(row0*80 + ch*16);

    float acc[2][4][4];
    #pragma unroll
    for (int i = 0; i < 2; ++i)
        #pragma unroll
        for (int j = 0; j < 4; ++j)
            #pragma unroll
            for (int r = 0; r < 4; ++r) acc[i][j][r] = 0.f;

    const int nk = K >> 5;
    auto load_stage = [&](int kt) {
        if (kt < nk) {
            uint32_t sb = tiles + (uint32_t)(kt & 1)*ST64;
            #pragma unroll
            for (int pl = 0; pl < 4; ++pl)
                #pragma unroll
                for (int rr = 0; rr < 2; ++rr) {
                    uint32_t dst = sb + pl*PL64 + dst0 + rr*32*80;
                    const bf16* src = Pb[pl] + (size_t)(rr*32)*K + kt*32;
                    asm volatile("cp.async.cg.shared.global [%0], [%1], 16;"
                                 :: "r"(dst), "l"(src));
                }
        }
        asm volatile("cp.async.commit_group;");
    };

    const int arow  = wm*32 + (lane & 15);
    const int acolx = (lane >> 4) << 3;
    const int brow  = wn*32 + ((lane >> 4) << 3) + (lane & 7);
    const int bcolx = ((lane >> 3) & 1) << 3;

    load_stage(0);
    load_stage(1);

    for (int kt = 0; kt < nk; ++kt) {
        uint32_t sb = tiles + (uint32_t)(kt & 1)*ST64;
        if (kt == nk - 1) { asm volatile("cp.async.wait_group 0;"); }
        else              { asm volatile("cp.async.wait_group 1;"); }
        __syncthreads();

        #pragma unroll
        for (int kc = 0; kc < 32; kc += 16) {
            uint32_t ah[2][4], al[2][4], bh[4][2], bl[4][2];
            #pragma unroll
            for (int mi = 0; mi < 2; ++mi) {
                uint32_t aaddr = sb + (arow + mi*16)*80 + (kc + acolx)*2;
                LDSM4(ah[mi][0], ah[mi][1], ah[mi][2], ah[mi][3], aaddr);
                LDSM4(al[mi][0], al[mi][1], al[mi][2], al[mi][3], aaddr + PL64);
            }
            #pragma unroll
            for (int nt = 0; nt < 2; ++nt) {
                uint32_t baddr = sb + 2*PL64 + (brow + nt*16)*80 + (kc + bcolx)*2;
                LDSM4(bh[nt*2][0], bh[nt*2][1], bh[nt*2+1][0], bh[nt*2+1][1], baddr);
                LDSM4(bl[nt*2][0], bl[nt*2][1], bl[nt*2+1][0], bl[nt*2+1][1], baddr + PL64);
            }
            #pragma unroll
            for (int mi = 0; mi < 2; ++mi)
                #pragma unroll
                for (int ni = 0; ni < 4; ++ni)
                    MMA_BF16(acc[mi][ni], ah[mi], bh[ni]);
            #pragma unroll
            for (int mi = 0; mi < 2; ++mi)
                #pragma unroll
                for (int ni = 0; ni < 4; ++ni)
                    MMA_BF16(acc[mi][ni], ah[mi], bl[ni]);
            #pragma unroll
            for (int mi = 0; mi < 2; ++mi)
                #pragma unroll
                for (int ni = 0; ni < 4; ++ni)
                    MMA_BF16(acc[mi][ni], al[mi], bh[ni]);
        }
        __syncthreads();
        load_stage(kt + 2);
    }

    const int fr = lane >> 2, fq = (lane & 3) << 1;
    #pragma unroll
    for (int mi = 0; mi < 2; ++mi) {
        #pragma unroll
        for (int ni = 0; ni < 4; ++ni) {
            int row = bm + wm*32 + mi*16 + fr;
            int col = bn + wn*32 + ni*8 + fq;
            #pragma unroll
            for (int r = 0; r < 4; ++r) {
                int rr = row + (r >> 1)*8;
                int cc = col + (r & 1);
                float val = acc[mi][ni][r];
                size_t ix = (size_t)rr * N + cc;
                if (EPI == 1) {
                    C[ix] += val;
                } else if (EPI == 2) {
                    float re = fmaxf(val, 0.f);
                    split_store1(re * re, &Ch[ix], &Cl[ix]);
                } else if (EPI == 3) {
                    C[ix] = 15.0f * tanhf(val * (1.0f/15.0f));
                } else {
                    C[ix] = val;
                }
            }
        }
    }
}

// ------------------------------------------------------------------
// value-embedding gate
// ------------------------------------------------------------------
__global__ void ve_kernel(const int* __restrict__ idx,
                          const float* __restrict__ ve_table,
                          const float* __restrict__ gate_w) {
    __shared__ float gates[KVHH];
    int row = blockIdx.x, tid = threadIdx.x;
    if (tid < KVHH*32) {
        int g = tid >> 5, lane = tid & 31;
        float p = g_xn[(size_t)row*DD + lane] * gate_w[g*32 + lane];
        p = warp_reduce_sum(p);
        if (lane == 0) gates[g] = 2.0f / (1.0f + expf(-p));
    }
    __syncthreads();
    int tok = idx[row];
    g_qkv[(size_t)row*QKVW + 1024 + tid] += gates[tid >> 6] *
        ve_table[(size_t)tok*256 + tid];
}

// ------------------------------------------------------------------
// fused RoPE + per-head rmsnorm for q AND k in one launch.
// 16 warps-of-work per row: head 0..11 -> q (offset head*64),
// head 12..15 -> k (offset DD + (head-12)*64).
// ------------------------------------------------------------------
__global__ void rope_norm_all_kernel(float* __restrict__ p) {
    int gw   = (blockIdx.x * blockDim.x + threadIdx.x) >> 5;
    int lane = threadIdx.x & 31;
    int row  = gw >> 4;
    int head = gw & 15;
    int t    = row & (TT-1);
    int off  = (head < HH) ? head*HDD : DD + (head - HH)*HDD;
    float* base = p + (size_t)row*QKVW + off;
    float a = base[lane];
    float b = base[lane + 32];
    float inv = 1.0f / powf(10000.0f, (float)lane * (1.0f/32.0f));
    float ang = (float)t * inv;
    float s, c;
    sincosf(ang, &s, &c);
    float na =  a*c + b*s;
    float nb = -a*s + b*c;
    float ss = warp_reduce_sum(na*na + nb*nb);
    float sc = rsqrtf(ss * (1.0f/HDD) + 1e-6f);
    base[lane]      = na * sc;
    base[lane + 32] = nb * sc;
}

// ------------------------------------------------------------------
// tiled attention, QT=16 -> 512 blocks for higher SM occupancy.
// block per (b, kvh, 16-query tile); 8 warps, each warp owns
// 2 queries x 3 heads.
// ------------------------------------------------------------------
#define QT 16
__global__ void __launch_bounds__(256) attn_kernel(int w) {
    __shared__ float sq[QT*3][64];
    __shared__ float sk[32][68];
    __shared__ float sv[32][68];

    int tid = threadIdx.x, lane = tid & 31, warp = tid >> 5;
    int blk = blockIdx.x;
    int qt = blk & 63;
    int g  = (blk >> 6) & 3;
    int b  = blk >> 8;
    int q0 = qt * QT;

    for (int it = tid; it < QT*3*16; it += 256) {
        int qh = it >> 4, ds = (it & 15) << 2;
        int q = qh / 3, hl = qh % 3;
        const float* qp = g_qkv + (size_t)(b*TT + q0 + q)*QKVW + (g*3 + hl)*HDD + ds;
        *(float4*)&sq[qh][ds] = *(const float4*)qp;
    }

    float m[6], l[6], a0[6], a1[6];
    #pragma unroll
    for (int p = 0; p < 6; ++p) { m[p] = -1e30f; l[p] = 0.f; a0[p] = 0.f; a1[p] = 0.f; }

    int jlo = q0 - w + 1; if (jlo < 0) jlo = 0;
    int js0 = jlo & ~31;
    __syncthreads();

    for (int js = js0; js < q0 + QT; js += 32) {
        for (int it = tid; it < 512; it += 256) {
            int key = it >> 4, ds = (it & 15) << 2;
            const float* kp = g_qkv + (size_t)(b*TT + js + key)*QKVW + DD + g*HDD + ds;
            *(float4*)&sk[key][ds] = *(const float4*)kp;
            *(float4*)&sv[key][ds] = *(const float4*)(kp + 256);
        }
        __syncthreads();

        #pragma unroll
        for (int qi = 0; qi < 2; ++qi) {
            int qq = warp*2 + qi;
            int t  = q0 + qq;
            int j  = js + lane;
            bool valid = (j <= t) && (t - j < w);
            float s0 = -1e30f, s1 = -1e30f, s2 = -1e30f;
            if (valid) {
                float d0 = 0.f, d1 = 0.f, d2 = 0.f;
                #pragma unroll
                for (int ds = 0; ds < 64; ds += 4) {
                    float4 kv = *(const float4*)&sk[lane][ds];
                    float4 qa = *(const float4*)&sq[qq*3+0][ds];
                    float4 qb = *(const float4*)&sq[qq*3+1][ds];
                    float4 qc = *(const float4*)&sq[qq*3+2][ds];
                    d0 += qa.x*kv.x + qa.y*kv.y + qa.z*kv.z + qa.w*kv.w;
                    d1 += qb.x*kv.x + qb.y*kv.y + qb.z*kv.z + qb.w*kv.w;
                    d2 += qc.x*kv.x + qc.y*kv.y + qc.z*kv.z + qc.w*kv.w;
                }
                s0 = d0*0.125f; s1 = d1*0.125f; s2 = d2*0.125f;
            }
            float pr0, pr1, pr2;
            #pragma unroll
            for (int hl = 0; hl < 3; ++hl) {
                int p = qi*3 + hl;
                float sc = (hl == 0) ? s0 : (hl == 1) ? s1 : s2;
                float cm = warp_reduce_max(sc);
                float nm = fmaxf(m[p], cm);
                float pr = valid ? __expf(sc - nm) : 0.f;
                float corr = __expf(m[p] - nm);
                float sl = warp_reduce_sum(pr);
                l[p]  = l[p]*corr + sl;
                a0[p] *= corr; a1[p] *= corr;
                m[p] = nm;
                if (hl == 0) pr0 = pr; else if (hl == 1) pr1 = pr; else pr2 = pr;
            }
            #pragma unroll 8
            for (int kk = 0; kk < 32; ++kk) {
                float v0 = sv[kk][lane], v1 = sv[kk][lane+32];
                float pa = __shfl_sync(0xffffffffu, pr0, kk);
                float pb = __shfl_sync(0xffffffffu, pr1, kk);
                float pc = __shfl_sync(0xffffffffu, pr2, kk);
                a0[qi*3+0] = fmaf(pa, v0, a0[qi*3+0]);
                a1[qi*3+0] = fmaf(pa, v1, a1[qi*3+0]);
                a0[qi*3+1] = fmaf(pb, v0, a0[qi*3+1]);
                a1[qi*3+1] = fmaf(pb, v1, a1[qi*3+1]);
                a0[qi*3+2] = fmaf(pc, v0, a0[qi*3+2]);
                a1[qi*3+2] = fmaf(pc, v1, a1[qi*3+2]);
            }
        }
        __syncthreads();
    }

    #pragma unroll
    for (int qi = 0; qi < 2; ++qi) {
        #pragma unroll
        for (int hl = 0; hl < 3; ++hl) {
            int p = qi*3 + hl;
            size_t off = (size_t)(b*TT + q0 + warp*2 + qi)*DD + (g*3 + hl)*HDD;
            float inv = 1.0f / l[p];
            split_store1(a0[p]*inv, &g_yh[off + lane],      &g_yl[off + lane]);
            split_store1(a1[p]*inv, &g_yh[off + lane + 32], &g_yl[off + lane + 32]);
        }
    }
}

// ------------------------------------------------------------------
// host launcher
// ------------------------------------------------------------------
extern "C" void kernel_launch(void* const* d_in, const int* in_sizes, int n_in,
                              void* d_out, int out_size) {
    (void)in_sizes; (void)n_in; (void)out_size;
    const int*   idx    = (const int*)  d_in[0];
    const float* wte    = (const float*)d_in[1];
    const float* Wq     = (const float*)d_in[2];
    const float* Wk     = (const float*)d_in[3];
    const float* Wv     = (const float*)d_in[4];
    const float* Wo     = (const float*)d_in[5];
    const float* Wfc    = (const float*)d_in[6];
    const float* Wproj  = (const float*)d_in[7];
    const float* vetab  = (const float*)d_in[8];
    const float* vegate = (const float*)d_in[9];
    const float* rl     = (const float*)d_in[10];
    const float* xl     = (const float*)d_in[11];
    const float* lm     = (const float*)d_in[12];
    float* out = (float*)d_out;

    float *px, *pqkv;
    bf16 *pxnh, *pxnl, *pyh, *pyl, *phh, *phl;
    bf16 *pwqkvh, *pwqkvl, *pwoh, *pwol, *pwfch, *pwfcl, *pwprh, *pwprl, *plmh, *plml;
    cudaGetSymbolAddress((void**)&px,    g_x);
    cudaGetSymbolAddress((void**)&pqkv,  g_qkv);
    cudaGetSymbolAddress((void**)&pxnh,  g_xnh);
    cudaGetSymbolAddress((void**)&pxnl,  g_xnl);
    cudaGetSymbolAddress((void**)&pyh,   g_yh);
    cudaGetSymbolAddress((void**)&pyl,   g_yl);
    cudaGetSymbolAddress((void**)&phh,   g_hh);
    cudaGetSymbolAddress((void**)&phl,   g_hl);
    cudaGetSymbolAddress((void**)&pwqkvh,g_wqkvh);
    cudaGetSymbolAddress((void**)&pwqkvl,g_wqkvl);
    cudaGetSymbolAddress((void**)&pwoh,  g_woh);
    cudaGetSymbolAddress((void**)&pwol,  g_wol);
    cudaGetSymbolAddress((void**)&pwfch, g_wfch);
    cudaGetSymbolAddress((void**)&pwfcl, g_wfcl);
    cudaGetSymbolAddress((void**)&pwprh, g_wprh);
    cudaGetSymbolAddress((void**)&pwprl, g_wprl);
    cudaGetSymbolAddress((void**)&plmh,  g_lmh);
    cudaGetSymbolAddress((void**)&plml,  g_lml);

    cudaFuncSetAttribute((const void*)gemm64_kernel<0>, cudaFuncAttributeMaxDynamicSharedMemorySize, GSMB64);
    cudaFuncSetAttribute((const void*)gemm64_kernel<1>, cudaFuncAttributeMaxDynamicSharedMemorySize, GSMB64);
    cudaFuncSetAttribute((const void*)gemm64_kernel<2>, cudaFuncAttributeMaxDynamicSharedMemorySize, GSMB64);
    cudaFuncSetAttribute((const void*)gemm64_kernel<3>, cudaFuncAttributeMaxDynamicSharedMemorySize, GSMB64);

    const int windows[LLAY] = {TT/2, TT, TT/2, TT, TT/2, TT};
    bf16* nb = (bf16*)0;
    int n4;

    // launches 1-3, then the profiled QKV GEMM at launch 4
    n4 = LLAY*QKVW*DD/4;  pack_split_qkv<<<(n4+255)/256, 256>>>(Wq, Wk, Wv);     // 1
    embed_norm_kernel<<<RR, 256>>>(idx, wte);                                    // 2
    resid_norm_kernel<<<RR, 256>>>(rl, xl, 0);                                   // 3
    gemm64_kernel<0><<<dim3(QKVW/64, RR/64), 128, GSMB64>>>(                     // 4
        pxnh, pxnl, pwqkvh, pwqkvl, pqkv, nb, nb, RR, QKVW, DD);

    // remaining weight splits
    n4 = LLAY*DD*DD/4;    split_kernel<<<(n4+255)/256, 256>>>(Wo,    pwoh,  pwol,  n4);
    n4 = LLAY*FF*DD/4;    split_kernel<<<(n4+255)/256, 256>>>(Wfc,   pwfch, pwfcl, n4);
    n4 = LLAY*DD*FF/4;    split_kernel<<<(n4+255)/256, 256>>>(Wproj, pwprh, pwprl, n4);
    n4 = VV*DD/4;         split_kernel<<<(n4+255)/256, 256>>>(lm,    plmh,  plml,  n4);

    for (int i = 0; i < LLAY; ++i) {
        if (i > 0) {
            resid_norm_kernel<<<RR, 256>>>(rl, xl, i);
            gemm64_kernel<0><<<dim3(QKVW/64, RR/64), 128, GSMB64>>>(
                pxnh, pxnl, pwqkvh + (size_t)i*QKVW*DD, pwqkvl + (size_t)i*QKVW*DD,
                pqkv, nb, nb, RR, QKVW, DD);
        }

        int slot = (i == 1) ? 0 : (i == 3) ? 1 : (i == 5) ? 2 : -1;
        if (slot >= 0)
            ve_kernel<<<RR, 256>>>(idx, vetab + (size_t)slot*VV*256,
                                   vegate + (size_t)slot*KVHH*32);

        rope_norm_all_kernel<<<(RR*16)/8, 256>>>(pqkv);

        attn_kernel<<<BB*KVHH*(TT/QT), 256>>>(windows[i]);

        gemm64_kernel<1><<<dim3(DD/64, RR/64), 128, GSMB64>>>(
            pyh, pyl, pwoh + (size_t)i*DD*DD, pwol + (size_t)i*DD*DD,
            px, nb, nb, RR, DD, DD);

        resid_norm_kernel<<<RR, 256>>>(rl, xl, -1);

        gemm64_kernel<2><<<dim3(FF/64, RR/64), 128, GSMB64>>>(
            pxnh, pxnl, pwfch + (size_t)i*FF*DD, pwfcl + (size_t)i*FF*DD,
            px, phh, phl, RR, FF, DD);

        gemm64_kernel<1><<<dim3(DD/64, RR/64), 128, GSMB64>>>(
            phh, phl, pwprh + (size_t)i*DD*FF, pwprl + (size_t)i*DD*FF,
            px, nb, nb, RR, DD, FF);
    }

    resid_norm_kernel<<<RR, 256>>>(rl, xl, -1);
    gemm64_kernel<3><<<dim3(VV/64, RR/64), 128, GSMB64>>>(
        pxnh, pxnl, plmh, plml, out, nb, nb, RR, VV, DD);
}

// round 17
// speedup vs baseline: 1.0801x; 1.0558x over previous
#include <cuda_runtime.h>
#include <cuda_bf16.h>
#include <math.h>
#include <stdint.h>

// ---- model constants ----
#define BB   2
#define TT   1024
#define RR   2048
#define DD   768
#define HH   12
#define KVHH 4
#define HDD  64
#define QKVW 1280
#define LLAY 6
#define VV   32000
#define FF   3072

typedef __nv_bfloat16 bf16;
typedef __nv_bfloat162 bf162;

// ---- scratch ----
__device__ float g_x  [RR*DD];
__device__ float g_x0 [RR*DD];
__device__ float g_xn [RR*DD];     // fp32 xn; only cols [0,32) consumed (ve gate)
__device__ float g_qkv[RR*QKVW];

__device__ bf16 g_xnh[RR*DD],  g_xnl[RR*DD];
__device__ bf16 g_yh [RR*DD],  g_yl [RR*DD];
__device__ bf16 g_hh [RR*FF],  g_hl [RR*FF];

__device__ bf16 g_wqkvh[LLAY*QKVW*DD], g_wqkvl[LLAY*QKVW*DD];
__device__ bf16 g_woh  [LLAY*DD*DD],   g_wol  [LLAY*DD*DD];
__device__ bf16 g_wfch [LLAY*FF*DD],   g_wfcl [LLAY*FF*DD];
__device__ bf16 g_wprh [LLAY*DD*FF],   g_wprl [LLAY*DD*FF];
__device__ bf16 g_lmh  [(size_t)VV*DD], g_lml [(size_t)VV*DD];

// ------------------------------------------------------------------
// helpers
// ------------------------------------------------------------------
__device__ __forceinline__ float block_reduce_sum_256(float v, float* sh) {
    int tid = threadIdx.x;
    sh[tid] = v;
    __syncthreads();
    #pragma unroll
    for (int s = 128; s > 0; s >>= 1) {
        if (tid < s) sh[tid] += sh[tid + s];
        __syncthreads();
    }
    return sh[0];
}
__device__ __forceinline__ float warp_reduce_sum(float v) {
    #pragma unroll
    for (int o = 16; o > 0; o >>= 1) v += __shfl_xor_sync(0xffffffffu, v, o);
    return v;
}
__device__ __forceinline__ float warp_reduce_max(float v) {
    #pragma unroll
    for (int o = 16; o > 0; o >>= 1) v = fmaxf(v, __shfl_xor_sync(0xffffffffu, v, o));
    return v;
}
__device__ __forceinline__ void split_store4(float4 v, bf16* hi, bf16* lo) {
    bf162 h0, h1, l0, l1;
    h0.x = __float2bfloat16_rn(v.x); h0.y = __float2bfloat16_rn(v.y);
    h1.x = __float2bfloat16_rn(v.z); h1.y = __float2bfloat16_rn(v.w);
    l0.x = __float2bfloat16_rn(v.x - __bfloat162float(h0.x));
    l0.y = __float2bfloat16_rn(v.y - __bfloat162float(h0.y));
    l1.x = __float2bfloat16_rn(v.z - __bfloat162float(h1.x));
    l1.y = __float2bfloat16_rn(v.w - __bfloat162float(h1.y));
    *(bf162*)hi = h0; *(bf162*)(hi + 2) = h1;
    *(bf162*)lo = l0; *(bf162*)(lo + 2) = l1;
}
__device__ __forceinline__ void split_store1(float v, bf16* hi, bf16* lo) {
    bf16 h = __float2bfloat16_rn(v);
    *hi = h;
    *lo = __float2bfloat16_rn(v - __bfloat162float(h));
}
__device__ __forceinline__ uint32_t smem_u32(const void* p) {
    uint32_t a;
    asm("{ .reg .u64 t; cvta.to.shared.u64 t, %1; cvt.u32.u64 %0, t; }" : "=r"(a) : "l"(p));
    return a;
}

// ------------------------------------------------------------------
// fp32 -> bf16 hi/lo split kernels
// ------------------------------------------------------------------
__global__ void split_kernel(const float* __restrict__ src,
                             bf16* __restrict__ hi, bf16* __restrict__ lo,
                             int n4) {
    int i = blockIdx.x * blockDim.x + threadIdx.x;
    if (i >= n4) return;
    float4 v = ((const float4*)src)[i];
    split_store4(v, hi + (size_t)i*4, lo + (size_t)i*4);
}
__global__ void pack_split_qkv(const float* __restrict__ Wq,
                               const float* __restrict__ Wk,
                               const float* __restrict__ Wv) {
    int i4 = blockIdx.x * blockDim.x + threadIdx.x;
    const int total4 = LLAY * QKVW * DD / 4;
    if (i4 >= total4) return;
    size_t e = (size_t)i4 * 4;
    int c   = (int)(e % DD);
    int r   = (int)((e / DD) % QKVW);
    int lyr = (int)(e / ((size_t)DD * QKVW));
    const float* srow;
    if (r < DD)            srow = Wq + (size_t)lyr*DD*DD  + (size_t)r*DD;
    else if (r < DD + 256) srow = Wk + (size_t)lyr*256*DD + (size_t)(r-DD)*DD;
    else                   srow = Wv + (size_t)lyr*256*DD + (size_t)(r-DD-256)*DD;
    float4 v = *(const float4*)(srow + c);
    split_store4(v, g_wqkvh + e, g_wqkvl + e);
}

// ------------------------------------------------------------------
// embedding + rmsnorm
// ------------------------------------------------------------------
__global__ void embed_norm_kernel(const int* __restrict__ idx,
                                  const float* __restrict__ wte) {
    __shared__ float sh[256];
    int row = blockIdx.x, tid = threadIdx.x;
    int tok = idx[row];
    const float* wrow = wte + (size_t)tok * DD;
    float v[3]; float ss = 0.f;
    #pragma unroll
    for (int j = 0; j < 3; ++j) { v[j] = wrow[tid + j*256]; ss += v[j]*v[j]; }
    float tot = block_reduce_sum_256(ss, sh);
    float sc = rsqrtf(tot * (1.0f/DD) + 1e-6f);
    #pragma unroll
    for (int j = 0; j < 3; ++j) {
        float o = v[j] * sc;
        g_x [(size_t)row*DD + tid + j*256] = o;
        g_x0[(size_t)row*DD + tid + j*256] = o;
    }
}

// ------------------------------------------------------------------
// residual mix + rmsnorm -> bf16 hi/lo planes (+ fp32 xn cols [0,32))
// ------------------------------------------------------------------
__global__ void resid_norm_kernel(const float* __restrict__ rl,
                                  const float* __restrict__ xl,
                                  int li) {
    __shared__ float sh[256];
    int row = blockIdx.x, tid = threadIdx.x;
    float rs = 1.f, xs = 0.f;
    if (li >= 0) { rs = rl[li]; xs = xl[li]; }
    float v[3]; float ss = 0.f;
    #pragma unroll
    for (int j = 0; j < 3; ++j) {
        size_t i = (size_t)row*DD + tid + j*256;
        float val = g_x[i]*rs;
        if (li >= 0) val += g_x0[i]*xs;
        v[j] = val; ss += val*val;
    }
    float tot = block_reduce_sum_256(ss, sh);
    float sc = rsqrtf(tot * (1.0f/DD) + 1e-6f);
    #pragma unroll
    for (int j = 0; j < 3; ++j) {
        size_t i = (size_t)row*DD + tid + j*256;
        if (li >= 0) g_x[i] = v[j];
        float o = v[j]*sc;
        if (j == 0 && tid < 32) g_xn[i] = o;    // only ve-gate columns needed
        split_store1(o, &g_xnh[i], &g_xnl[i]);
    }
}

#define MMA_BF16(d, a, b)                                                     \
    asm volatile("mma.sync.aligned.m16n8k16.row.col.f32.bf16.bf16.f32 "       \
                 "{%0,%1,%2,%3},{%4,%5,%6,%7},{%8,%9},{%0,%1,%2,%3};"         \
                 : "+f"(d[0]), "+f"(d[1]), "+f"(d[2]), "+f"(d[3])             \
                 : "r"(a[0]), "r"(a[1]), "r"(a[2]), "r"(a[3]),                \
                   "r"(b[0]), "r"(b[1]));

#define LDSM4(r0, r1, r2, r3, addr)                                           \
    asm volatile("ldmatrix.sync.aligned.m8n8.x4.shared.b16 {%0,%1,%2,%3},[%4];" \
                 : "=r"(r0), "=r"(r1), "=r"(r2), "=r"(r3) : "r"(addr));

// ------------------------------------------------------------------
// 64x64 CTA-tile GEMM, 128 threads (4 warps, each 32x32), BK=32,
// 2-stage cp.async, 40KB smem (R12 proven config) + split-K support:
// blockIdx.z selects a K-chunk of length klen; EPI=1 accumulates with
// atomicAdd so multiple K-chunks combine correctly.
// C[M,N] (+)= A[M,K]*B[N,K]^T  via Ah*Bh + Ah*Bl + Al*Bh.
// EPI: 0 store, 1 atomic-accumulate, 2 relu^2 -> bf16 hi/lo, 3 softcap
// ------------------------------------------------------------------
#define PL64   5120                 // 64 rows * 80 bytes
#define ST64   (4*PL64)             // 20480
#define GSMB64 (2*ST64)             // 40960

template<int EPI>
__global__ void __launch_bounds__(128, 5)
gemm64_kernel(const bf16* __restrict__ Ah, const bf16* __restrict__ Al,
              const bf16* __restrict__ Bh, const bf16* __restrict__ Bl,
              float* __restrict__ C, bf16* __restrict__ Ch, bf16* __restrict__ Cl,
              int M, int N, int K, int klen) {
    extern __shared__ char dsm[];
    const uint32_t tiles = smem_u32(dsm);

    const int tid = threadIdx.x, lane = tid & 31, warp = tid >> 5;
    const int wm = warp & 1, wn = warp >> 1;
    const int bm = blockIdx.y * 64, bn = blockIdx.x * 64;
    const int koff = blockIdx.z * klen;

    const int row0 = tid >> 2;          // 0..31
    const int ch   = tid & 3;
    const bf16* Pb[4] = { Ah + (size_t)(bm + row0)*K + koff + ch*8,
                          Al + (size_t)(bm + row0)*K + koff + ch*8,
                          Bh + (size_t)(bn + row0)*K + koff + ch*8,
                          Bl + (size_t)(bn + row0)*K + koff + ch*8 };
    const uint32_t dst0 = (uint32_t)(row0*80 + ch*16);

    float acc[2][4][4];
    #pragma unroll
    for (int i = 0; i < 2; ++i)
        #pragma unroll
        for (int j = 0; j < 4; ++j)
            #pragma unroll
            for (int r = 0; r < 4; ++r) acc[i][j][r] = 0.f;

    const int nk = klen >> 5;
    auto load_stage = [&](int kt) {
        if (kt < nk) {
            uint32_t sb = tiles + (uint32_t)(kt & 1)*ST64;
            #pragma unroll
            for (int pl = 0; pl < 4; ++pl)
                #pragma unroll
                for (int rr = 0; rr < 2; ++rr) {
                    uint32_t dst = sb + pl*PL64 + dst0 + rr*32*80;
                    const bf16* src = Pb[pl] + (size_t)(rr*32)*K + kt*32;
                    asm volatile("cp.async.cg.shared.global [%0], [%1], 16;"
                                 :: "r"(dst), "l"(src));
                }
        }
        asm volatile("cp.async.commit_group;");
    };

    const int arow  = wm*32 + (lane & 15);
    const int acolx = (lane >> 4) << 3;
    const int brow  = wn*32 + ((lane >> 4) << 3) + (lane & 7);
    const int bcolx = ((lane >> 3) & 1) << 3;

    load_stage(0);
    load_stage(1);

    for (int kt = 0; kt < nk; ++kt) {
        uint32_t sb = tiles + (uint32_t)(kt & 1)*ST64;
        if (kt == nk - 1) { asm volatile("cp.async.wait_group 0;"); }
        else              { asm volatile("cp.async.wait_group 1;"); }
        __syncthreads();

        #pragma unroll
        for (int kc = 0; kc < 32; kc += 16) {
            uint32_t ah[2][4], al[2][4], bh[4][2], bl[4][2];
            #pragma unroll
            for (int mi = 0; mi < 2; ++mi) {
                uint32_t aaddr = sb + (arow + mi*16)*80 + (kc + acolx)*2;
                LDSM4(ah[mi][0], ah[mi][1], ah[mi][2], ah[mi][3], aaddr);
                LDSM4(al[mi][0], al[mi][1], al[mi][2], al[mi][3], aaddr + PL64);
            }
            #pragma unroll
            for (int nt = 0; nt < 2; ++nt) {
                uint32_t baddr = sb + 2*PL64 + (brow + nt*16)*80 + (kc + bcolx)*2;
                LDSM4(bh[nt*2][0], bh[nt*2][1], bh[nt*2+1][0], bh[nt*2+1][1], baddr);
                LDSM4(bl[nt*2][0], bl[nt*2][1], bl[nt*2+1][0], bl[nt*2+1][1], baddr + PL64);
            }
            #pragma unroll
            for (int mi = 0; mi < 2; ++mi)
                #pragma unroll
                for (int ni = 0; ni < 4; ++ni)
                    MMA_BF16(acc[mi][ni], ah[mi], bh[ni]);
            #pragma unroll
            for (int mi = 0; mi < 2; ++mi)
                #pragma unroll
                for (int ni = 0; ni < 4; ++ni)
                    MMA_BF16(acc[mi][ni], ah[mi], bl[ni]);
            #pragma unroll
            for (int mi = 0; mi < 2; ++mi)
                #pragma unroll
                for (int ni = 0; ni < 4; ++ni)
                    MMA_BF16(acc[mi][ni], al[mi], bh[ni]);
        }
        __syncthreads();
        load_stage(kt + 2);
    }

    const int fr = lane >> 2, fq = (lane & 3) << 1;
    #pragma unroll
    for (int mi = 0; mi < 2; ++mi) {
        #pragma unroll
        for (int ni = 0; ni < 4; ++ni) {
            int row = bm + wm*32 + mi*16 + fr;
            int col = bn + wn*32 + ni*8 + fq;
            #pragma unroll
            for (int r = 0; r < 4; ++r) {
                int rr = row + (r >> 1)*8;
                int cc = col + (r & 1);
                float val = acc[mi][ni][r];
                size_t ix = (size_t)rr * N + cc;
                if (EPI == 1) {
                    atomicAdd(&C[ix], val);
                } else if (EPI == 2) {
                    float re = fmaxf(val, 0.f);
                    split_store1(re * re, &Ch[ix], &Cl[ix]);
                } else if (EPI == 3) {
                    C[ix] = 15.0f * tanhf(val * (1.0f/15.0f));
                } else {
                    C[ix] = val;
                }
            }
        }
    }
}

// ------------------------------------------------------------------
// value-embedding gate
// ------------------------------------------------------------------
__global__ void ve_kernel(const int* __restrict__ idx,
                          const float* __restrict__ ve_table,
                          const float* __restrict__ gate_w) {
    __shared__ float gates[KVHH];
    int row = blockIdx.x, tid = threadIdx.x;
    if (tid < KVHH*32) {
        int g = tid >> 5, lane = tid & 31;
        float p = g_xn[(size_t)row*DD + lane] * gate_w[g*32 + lane];
        p = warp_reduce_sum(p);
        if (lane == 0) gates[g] = 2.0f / (1.0f + expf(-p));
    }
    __syncthreads();
    int tok = idx[row];
    g_qkv[(size_t)row*QKVW + 1024 + tid] += gates[tid >> 6] *
        ve_table[(size_t)tok*256 + tid];
}

// ------------------------------------------------------------------
// fused RoPE + per-head rmsnorm for q AND k in one launch.
// ------------------------------------------------------------------
__global__ void rope_norm_all_kernel(float* __restrict__ p) {
    int gw   = (blockIdx.x * blockDim.x + threadIdx.x) >> 5;
    int lane = threadIdx.x & 31;
    int row  = gw >> 4;
    int head = gw & 15;
    int t    = row & (TT-1);
    int off  = (head < HH) ? head*HDD : DD + (head - HH)*HDD;
    float* base = p + (size_t)row*QKVW + off;
    float a = base[lane];
    float b = base[lane + 32];
    float inv = 1.0f / powf(10000.0f, (float)lane * (1.0f/32.0f));
    float ang = (float)t * inv;
    float s, c;
    sincosf(ang, &s, &c);
    float na =  a*c + b*s;
    float nb = -a*s + b*c;
    float ss = warp_reduce_sum(na*na + nb*nb);
    float sc = rsqrtf(ss * (1.0f/HDD) + 1e-6f);
    base[lane]      = na * sc;
    base[lane + 32] = nb * sc;
}

// ------------------------------------------------------------------
// tiled attention, QT=16 -> 512 blocks for higher SM occupancy.
// ------------------------------------------------------------------
#define QT 16
__global__ void __launch_bounds__(256) attn_kernel(int w) {
    __shared__ float sq[QT*3][64];
    __shared__ float sk[32][68];
    __shared__ float sv[32][68];

    int tid = threadIdx.x, lane = tid & 31, warp = tid >> 5;
    int blk = blockIdx.x;
    int qt = blk & 63;
    int g  = (blk >> 6) & 3;
    int b  = blk >> 8;
    int q0 = qt * QT;

    for (int it = tid; it < QT*3*16; it += 256) {
        int qh = it >> 4, ds = (it & 15) << 2;
        int q = qh / 3, hl = qh % 3;
        const float* qp = g_qkv + (size_t)(b*TT + q0 + q)*QKVW + (g*3 + hl)*HDD + ds;
        *(float4*)&sq[qh][ds] = *(const float4*)qp;
    }

    float m[6], l[6], a0[6], a1[6];
    #pragma unroll
    for (int p = 0; p < 6; ++p) { m[p] = -1e30f; l[p] = 0.f; a0[p] = 0.f; a1[p] = 0.f; }

    int jlo = q0 - w + 1; if (jlo < 0) jlo = 0;
    int js0 = jlo & ~31;
    __syncthreads();

    for (int js = js0; js < q0 + QT; js += 32) {
        for (int it = tid; it < 512; it += 256) {
            int key = it >> 4, ds = (it & 15) << 2;
            const float* kp = g_qkv + (size_t)(b*TT + js + key)*QKVW + DD + g*HDD + ds;
            *(float4*)&sk[key][ds] = *(const float4*)kp;
            *(float4*)&sv[key][ds] = *(const float4*)(kp + 256);
        }
        __syncthreads();

        #pragma unroll
        for (int qi = 0; qi < 2; ++qi) {
            int qq = warp*2 + qi;
            int t  = q0 + qq;
            int j  = js + lane;
            bool valid = (j <= t) && (t - j < w);
            float s0 = -1e30f, s1 = -1e30f, s2 = -1e30f;
            if (valid) {
                float d0 = 0.f, d1 = 0.f, d2 = 0.f;
                #pragma unroll
                for (int ds = 0; ds < 64; ds += 4) {
                    float4 kv = *(const float4*)&sk[lane][ds];
                    float4 qa = *(const float4*)&sq[qq*3+0][ds];
                    float4 qb = *(const float4*)&sq[qq*3+1][ds];
                    float4 qc = *(const float4*)&sq[qq*3+2][ds];
                    d0 += qa.x*kv.x + qa.y*kv.y + qa.z*kv.z + qa.w*kv.w;
                    d1 += qb.x*kv.x + qb.y*kv.y + qb.z*kv.z + qb.w*kv.w;
                    d2 += qc.x*kv.x + qc.y*kv.y + qc.z*kv.z + qc.w*kv.w;
                }
                s0 = d0*0.125f; s1 = d1*0.125f; s2 = d2*0.125f;
            }
            float pr0, pr1, pr2;
            #pragma unroll
            for (int hl = 0; hl < 3; ++hl) {
                int p = qi*3 + hl;
                float sc = (hl == 0) ? s0 : (hl == 1) ? s1 : s2;
                float cm = warp_reduce_max(sc);
                float nm = fmaxf(m[p], cm);
                float pr = valid ? __expf(sc - nm) : 0.f;
                float corr = __expf(m[p] - nm);
                float sl = warp_reduce_sum(pr);
                l[p]  = l[p]*corr + sl;
                a0[p] *= corr; a1[p] *= corr;
                m[p] = nm;
                if (hl == 0) pr0 = pr; else if (hl == 1) pr1 = pr; else pr2 = pr;
            }
            #pragma unroll 8
            for (int kk = 0; kk < 32; ++kk) {
                float v0 = sv[kk][lane], v1 = sv[kk][lane+32];
                float pa = __shfl_sync(0xffffffffu, pr0, kk);
                float pb = __shfl_sync(0xffffffffu, pr1, kk);
                float pc = __shfl_sync(0xffffffffu, pr2, kk);
                a0[qi*3+0] = fmaf(pa, v0, a0[qi*3+0]);
                a1[qi*3+0] = fmaf(pa, v1, a1[qi*3+0]);
                a0[qi*3+1] = fmaf(pb, v0, a0[qi*3+1]);
                a1[qi*3+1] = fmaf(pb, v1, a1[qi*3+1]);
                a0[qi*3+2] = fmaf(pc, v0, a0[qi*3+2]);
                a1[qi*3+2] = fmaf(pc, v1, a1[qi*3+2]);
            }
        }
        __syncthreads();
    }

    #pragma unroll
    for (int qi = 0; qi < 2; ++qi) {
        #pragma unroll
        for (int hl = 0; hl < 3; ++hl) {
            int p = qi*3 + hl;
            size_t off = (size_t)(b*TT + q0 + warp*2 + qi)*DD + (g*3 + hl)*HDD;
            float inv = 1.0f / l[p];
            split_store1(a0[p]*inv, &g_yh[off + lane],      &g_yl[off + lane]);
            split_store1(a1[p]*inv, &g_yh[off + lane + 32], &g_yl[off + lane + 32]);
        }
    }
}

// ------------------------------------------------------------------
// host launcher
// ------------------------------------------------------------------
extern "C" void kernel_launch(void* const* d_in, const int* in_sizes, int n_in,
                              void* d_out, int out_size) {
    (void)in_sizes; (void)n_in; (void)out_size;
    const int*   idx    = (const int*)  d_in[0];
    const float* wte    = (const float*)d_in[1];
    const float* Wq     = (const float*)d_in[2];
    const float* Wk     = (const float*)d_in[3];
    const float* Wv     = (const float*)d_in[4];
    const float* Wo     = (const float*)d_in[5];
    const float* Wfc    = (const float*)d_in[6];
    const float* Wproj  = (const float*)d_in[7];
    const float* vetab  = (const float*)d_in[8];
    const float* vegate = (const float*)d_in[9];
    const float* rl     = (const float*)d_in[10];
    const float* xl     = (const float*)d_in[11];
    const float* lm     = (const float*)d_in[12];
    float* out = (float*)d_out;

    float *px, *pqkv;
    bf16 *pxnh, *pxnl, *pyh, *pyl, *phh, *phl;
    bf16 *pwqkvh, *pwqkvl, *pwoh, *pwol, *pwfch, *pwfcl, *pwprh, *pwprl, *plmh, *plml;
    cudaGetSymbolAddress((void**)&px,    g_x);
    cudaGetSymbolAddress((void**)&pqkv,  g_qkv);
    cudaGetSymbolAddress((void**)&pxnh,  g_xnh);
    cudaGetSymbolAddress((void**)&pxnl,  g_xnl);
    cudaGetSymbolAddress((void**)&pyh,   g_yh);
    cudaGetSymbolAddress((void**)&pyl,   g_yl);
    cudaGetSymbolAddress((void**)&phh,   g_hh);
    cudaGetSymbolAddress((void**)&phl,   g_hl);
    cudaGetSymbolAddress((void**)&pwqkvh,g_wqkvh);
    cudaGetSymbolAddress((void**)&pwqkvl,g_wqkvl);
    cudaGetSymbolAddress((void**)&pwoh,  g_woh);
    cudaGetSymbolAddress((void**)&pwol,  g_wol);
    cudaGetSymbolAddress((void**)&pwfch, g_wfch);
    cudaGetSymbolAddress((void**)&pwfcl, g_wfcl);
    cudaGetSymbolAddress((void**)&pwprh, g_wprh);
    cudaGetSymbolAddress((void**)&pwprl, g_wprl);
    cudaGetSymbolAddress((void**)&plmh,  g_lmh);
    cudaGetSymbolAddress((void**)&plml,  g_lml);

    cudaFuncSetAttribute((const void*)gemm64_kernel<0>, cudaFuncAttributeMaxDynamicSharedMemorySize, GSMB64);
    cudaFuncSetAttribute((const void*)gemm64_kernel<1>, cudaFuncAttributeMaxDynamicSharedMemorySize, GSMB64);
    cudaFuncSetAttribute((const void*)gemm64_kernel<2>, cudaFuncAttributeMaxDynamicSharedMemorySize, GSMB64);
    cudaFuncSetAttribute((const void*)gemm64_kernel<3>, cudaFuncAttributeMaxDynamicSharedMemorySize, GSMB64);

    const int windows[LLAY] = {TT/2, TT, TT/2, TT, TT/2, TT};
    bf16* nb = (bf16*)0;
    int n4;

    // launches 1-3, then the profiled QKV GEMM at launch 4
    n4 = LLAY*QKVW*DD/4;  pack_split_qkv<<<(n4+255)/256, 256>>>(Wq, Wk, Wv);     // 1
    embed_norm_kernel<<<RR, 256>>>(idx, wte);                                    // 2
    resid_norm_kernel<<<RR, 256>>>(rl, xl, 0);                                   // 3
    gemm64_kernel<0><<<dim3(QKVW/64, RR/64), 128, GSMB64>>>(                     // 4
        pxnh, pxnl, pwqkvh, pwqkvl, pqkv, nb, nb, RR, QKVW, DD, DD);

    // remaining weight splits
    n4 = LLAY*DD*DD/4;    split_kernel<<<(n4+255)/256, 256>>>(Wo,    pwoh,  pwol,  n4);
    n4 = LLAY*FF*DD/4;    split_kernel<<<(n4+255)/256, 256>>>(Wfc,   pwfch, pwfcl, n4);
    n4 = LLAY*DD*FF/4;    split_kernel<<<(n4+255)/256, 256>>>(Wproj, pwprh, pwprl, n4);
    n4 = VV*DD/4;         split_kernel<<<(n4+255)/256, 256>>>(lm,    plmh,  plml,  n4);

    for (int i = 0; i < LLAY; ++i) {
        if (i > 0) {
            resid_norm_kernel<<<RR, 256>>>(rl, xl, i);
            gemm64_kernel<0><<<dim3(QKVW/64, RR/64), 128, GSMB64>>>(
                pxnh, pxnl, pwqkvh + (size_t)i*QKVW*DD, pwqkvl + (size_t)i*QKVW*DD,
                pqkv, nb, nb, RR, QKVW, DD, DD);
        }

        int slot = (i == 1) ? 0 : (i == 3) ? 1 : (i == 5) ? 2 : -1;
        if (slot >= 0)
            ve_kernel<<<RR, 256>>>(idx, vetab + (size_t)slot*VV*256,
                                   vegate + (size_t)slot*KVHH*32);

        rope_norm_all_kernel<<<(RR*16)/8, 256>>>(pqkv);

        attn_kernel<<<BB*KVHH*(TT/QT), 256>>>(windows[i]);

        // Wo: split-K x2 -> 768 CTAs
        gemm64_kernel<1><<<dim3(DD/64, RR/64, 2), 128, GSMB64>>>(
            pyh, pyl, pwoh + (size_t)i*DD*DD, pwol + (size_t)i*DD*DD,
            px, nb, nb, RR, DD, DD, DD/2);

        resid_norm_kernel<<<RR, 256>>>(rl, xl, -1);

        gemm64_kernel<2><<<dim3(FF/64, RR/64), 128, GSMB64>>>(
            pxnh, pxnl, pwfch + (size_t)i*FF*DD, pwfcl + (size_t)i*FF*DD,
            px, phh, phl, RR, FF, DD, DD);

        // Wproj: split-K x4 -> 1536 CTAs
        gemm64_kernel<1><<<dim3(DD/64, RR/64, 4), 128, GSMB64>>>(
            phh, phl, pwprh + (size_t)i*DD*FF, pwprl + (size_t)i*DD*FF,
            px, nb, nb, RR, DD, FF, FF/4);
    }

    resid_norm_kernel<<<RR, 256>>>(rl, xl, -1);
    gemm64_kernel<3><<<dim3(VV/64, RR/64), 128, GSMB64>>>(
        pxnh, pxnl, plmh, plml, out, nb, nb, RR, VV, DD, DD);
}